// round 1
// baseline (speedup 1.0000x reference)
#include <cuda_runtime.h>
#include <cuda_bf16.h>

// Problem constants
#define C_DIM   192
#define HEADS   8
#define HD      24          // head dim = 192/8
#define HH      64
#define WW      64
#define NPIX    4096        // 64*64
#define QKV_CH  576         // 3*C

// ---------------- scratch (static device globals; no allocs) ----------------
__device__ float g_xln[C_DIM * NPIX];        // 3 MB
__device__ float g_qkv[QKV_CH * NPIX];       // 9 MB
__device__ float g_qkvdw[QKV_CH * NPIX];     // 9 MB
__device__ float g_att[C_DIM * NPIX];        // 3 MB

// ---------------- small helpers ----------------
__device__ __forceinline__ float ex2f_fast(float x) {
    float r;
    asm("ex2.approx.f32 %0, %1;" : "=f"(r) : "f"(x));
    return r;
}

// packed fp32x2 fma: (x,y) += (ax,ay)*(bx,by)
__device__ __forceinline__ void fma2(float& x, float& y, float ax, float ay, float bx, float by) {
    asm("{\n\t"
        ".reg .b64 a, b, c;\n\t"
        "mov.b64 a, {%2, %3};\n\t"
        "mov.b64 b, {%4, %5};\n\t"
        "mov.b64 c, {%0, %1};\n\t"
        "fma.rn.f32x2 c, a, b, c;\n\t"
        "mov.b64 {%0, %1}, c;\n\t"
        "}"
        : "+f"(x), "+f"(y)
        : "f"(ax), "f"(ay), "f"(bx), "f"(by));
}

// packed fp32x2 scale: (x,y) *= a
__device__ __forceinline__ void mul2(float& x, float& y, float a) {
    asm("{\n\t"
        ".reg .b64 c, s;\n\t"
        "mov.b64 c, {%0, %1};\n\t"
        "mov.b64 s, {%2, %2};\n\t"
        "mul.rn.f32x2 c, c, s;\n\t"
        "mov.b64 {%0, %1}, c;\n\t"
        "}"
        : "+f"(x), "+f"(y)
        : "f"(a));
}

// ---------------- Kernel 1: per-pixel LayerNorm over channels ----------------
__global__ void ln_kernel(const float* __restrict__ x,
                          const float* __restrict__ gamma,
                          const float* __restrict__ beta,
                          float* __restrict__ xln) {
    int p = blockIdx.x * blockDim.x + threadIdx.x;
    if (p >= NPIX) return;
    float s = 0.f, s2 = 0.f;
    #pragma unroll 8
    for (int c = 0; c < C_DIM; c++) {
        float v = x[c * NPIX + p];
        s += v;
        s2 = fmaf(v, v, s2);
    }
    const float invC = 1.0f / (float)C_DIM;
    float mean = s * invC;
    float var = s2 * invC - mean * mean;
    float inv = rsqrtf(var + 1e-5f);
    #pragma unroll 8
    for (int c = 0; c < C_DIM; c++) {
        float v = (x[c * NPIX + p] - mean) * inv;
        xln[c * NPIX + p] = fmaf(v, gamma[c], beta[c]);
    }
}

// ---------------- Kernel 2: GEMM  Y[O,N] = W[O,C] @ X[C,N] (+ optional residual) ----
// block tile 64x64, 256 threads, 4x4 micro-tile, K step 16.
__global__ __launch_bounds__(256) void gemm_kernel(
        const float* __restrict__ W, const float* __restrict__ X,
        const float* __restrict__ resid, float* __restrict__ Y,
        int O, int C, int N) {
    __shared__ __align__(16) float As[16][68];   // [k][o], padded
    __shared__ __align__(16) float Bs[16][64];   // [k][n]
    int tid = threadIdx.x;
    int tx = tid & 15;       // N dir
    int ty = tid >> 4;       // O dir
    int o0 = blockIdx.y * 64;
    int n0 = blockIdx.x * 64;

    float acc[4][4];
    #pragma unroll
    for (int i = 0; i < 4; i++)
        #pragma unroll
        for (int j = 0; j < 4; j++) acc[i][j] = 0.f;

    for (int k0 = 0; k0 < C; k0 += 16) {
        // A tile: W[o0+row][k0 + col..col+3]
        {
            int row = tid >> 2;
            int col = (tid & 3) * 4;
            float4 a = *(const float4*)&W[(o0 + row) * C + k0 + col];
            As[col + 0][row] = a.x;
            As[col + 1][row] = a.y;
            As[col + 2][row] = a.z;
            As[col + 3][row] = a.w;
        }
        // B tile: X[k0+row][n0 + col..col+3]
        {
            int row = tid >> 4;
            int col = (tid & 15) * 4;
            *(float4*)&Bs[row][col] = *(const float4*)&X[(k0 + row) * N + n0 + col];
        }
        __syncthreads();
        #pragma unroll
        for (int k = 0; k < 16; k++) {
            float4 a4 = *(const float4*)&As[k][ty * 4];
            float4 b4 = *(const float4*)&Bs[k][tx * 4];
            float a[4] = {a4.x, a4.y, a4.z, a4.w};
            float b[4] = {b4.x, b4.y, b4.z, b4.w};
            #pragma unroll
            for (int i = 0; i < 4; i++)
                #pragma unroll
                for (int j = 0; j < 4; j++)
                    acc[i][j] = fmaf(a[i], b[j], acc[i][j]);
        }
        __syncthreads();
    }

    #pragma unroll
    for (int i = 0; i < 4; i++) {
        int o = o0 + ty * 4 + i;
        int n = n0 + tx * 4;
        float4 r = make_float4(acc[i][0], acc[i][1], acc[i][2], acc[i][3]);
        if (resid) {
            float4 rv = *(const float4*)&resid[o * N + n];
            r.x += rv.x; r.y += rv.y; r.z += rv.z; r.w += rv.w;
        }
        *(float4*)&Y[o * N + n] = r;
    }
}

// ---------------- Kernel 3: depthwise 3x3 conv + bias ----------------
__global__ void dwconv_kernel(const float* __restrict__ in,
                              const float* __restrict__ w,
                              const float* __restrict__ b,
                              float* __restrict__ out) {
    int idx = blockIdx.x * blockDim.x + threadIdx.x;
    if (idx >= QKV_CH * NPIX) return;
    int xx = idx & (WW - 1);
    int yy = (idx >> 6) & (HH - 1);
    int ch = idx >> 12;
    const float* wp = &w[ch * 9];
    const float* base = &in[ch * NPIX];
    float acc = b[ch];
    #pragma unroll
    for (int dy = -1; dy <= 1; dy++) {
        int y2 = yy + dy;
        if (y2 < 0 || y2 >= HH) continue;
        #pragma unroll
        for (int dx = -1; dx <= 1; dx++) {
            int x2 = xx + dx;
            if (x2 < 0 || x2 >= WW) continue;
            acc = fmaf(base[y2 * WW + x2], wp[(dy + 1) * 3 + (dx + 1)], acc);
        }
    }
    out[idx] = acc;
}

// ---------------- Kernel 4: flash attention, 1 thread = 1 query row ----------------
// q[b,h,d,n]: channel h*24+d of qkvdw rows [0,192); k at +192; v at +384.
// attn[n,m] = sum_d q[d,n] k[d,m] * temp[h]; softmax over m; out[d,n] = sum_m p v[d,m].
#define ATT_TILE 64
__global__ __launch_bounds__(128) void attn_kernel(
        const float* __restrict__ qkv, const float* __restrict__ temp,
        float* __restrict__ out) {
    __shared__ __align__(16) float Ks[ATT_TILE][24];
    __shared__ __align__(16) float Vs[ATT_TILE][24];

    int h = blockIdx.y;
    int n = blockIdx.x * 128 + threadIdx.x;
    const float scale = temp[h] * 1.4426950408889634f;  // fold temperature * log2(e)

    float q[24];
    #pragma unroll
    for (int d = 0; d < 24; d++)
        q[d] = qkv[(h * HD + d) * NPIX + n] * scale;

    float o[24];
    #pragma unroll
    for (int d = 0; d < 24; d++) o[d] = 0.f;
    float m = -1e30f, l = 0.f;

    const float* kg = &qkv[(C_DIM + h * HD) * NPIX];
    const float* vg = &qkv[(2 * C_DIM + h * HD) * NPIX];

    for (int m0 = 0; m0 < NPIX; m0 += ATT_TILE) {
        // cooperative load, global coalesced, smem [j][d]
        #pragma unroll
        for (int e = threadIdx.x; e < ATT_TILE * 24; e += 128) {
            int d = e >> 6;
            int j = e & (ATT_TILE - 1);
            Ks[j][d] = kg[d * NPIX + m0 + j];
            Vs[j][d] = vg[d * NPIX + m0 + j];
        }
        __syncthreads();

        #pragma unroll 1
        for (int c0 = 0; c0 < ATT_TILE; c0 += 16) {
            float s[16];
            // S = q . K  (broadcast smem reads, packed fp32x2 fma)
            #pragma unroll
            for (int jj = 0; jj < 16; jj++) {
                const float4* kp = (const float4*)&Ks[c0 + jj][0];
                float ax = 0.f, ay = 0.f, bx = 0.f, by = 0.f;
                #pragma unroll
                for (int i = 0; i < 6; i += 2) {
                    float4 k0v = kp[i];
                    float4 k1v = kp[i + 1];
                    fma2(ax, ay, q[4 * i + 0], q[4 * i + 1], k0v.x, k0v.y);
                    fma2(bx, by, q[4 * i + 2], q[4 * i + 3], k0v.z, k0v.w);
                    fma2(ax, ay, q[4 * i + 4], q[4 * i + 5], k1v.x, k1v.y);
                    fma2(bx, by, q[4 * i + 6], q[4 * i + 7], k1v.z, k1v.w);
                }
                s[jj] = (ax + bx) + (ay + by);
            }
            // online softmax update
            float mx = m;
            #pragma unroll
            for (int jj = 0; jj < 16; jj++) mx = fmaxf(mx, s[jj]);
            float alpha = ex2f_fast(m - mx);
            m = mx;
            l *= alpha;
            #pragma unroll
            for (int i = 0; i < 12; i++) mul2(o[2 * i], o[2 * i + 1], alpha);
            // accumulate P @ V
            #pragma unroll
            for (int jj = 0; jj < 16; jj++) {
                float p = ex2f_fast(s[jj] - m);
                l += p;
                const float4* vp = (const float4*)&Vs[c0 + jj][0];
                #pragma unroll
                for (int i = 0; i < 6; i++) {
                    float4 vv = vp[i];
                    fma2(o[4 * i + 0], o[4 * i + 1], p, p, vv.x, vv.y);
                    fma2(o[4 * i + 2], o[4 * i + 3], p, p, vv.z, vv.w);
                }
            }
        }
        __syncthreads();
    }

    float invl = 1.0f / l;
    #pragma unroll
    for (int d = 0; d < 24; d++)
        out[(h * HD + d) * NPIX + n] = o[d] * invl;
}

// ---------------- launch ----------------
extern "C" void kernel_launch(void* const* d_in, const int* in_sizes, int n_in,
                              void* d_out, int out_size) {
    const float* x      = (const float*)d_in[0];   // [192,4096]
    const float* gamma  = (const float*)d_in[1];   // [192]
    const float* beta   = (const float*)d_in[2];   // [192]
    const float* w_qkv  = (const float*)d_in[3];   // [576,192]
    const float* w_dw   = (const float*)d_in[4];   // [576,9]
    const float* b_dw   = (const float*)d_in[5];   // [576]
    const float* w_proj = (const float*)d_in[6];   // [192,192]
    const float* temper = (const float*)d_in[7];   // [8]
    float* out = (float*)d_out;

    float *xln, *qkvb, *qkvdw, *att;
    cudaGetSymbolAddress((void**)&xln,   g_xln);
    cudaGetSymbolAddress((void**)&qkvb,  g_qkv);
    cudaGetSymbolAddress((void**)&qkvdw, g_qkvdw);
    cudaGetSymbolAddress((void**)&att,   g_att);

    // 1. LayerNorm
    ln_kernel<<<NPIX / 256, 256>>>(x, gamma, beta, xln);

    // 2. qkv = w_qkv @ xln   [576,4096]
    {
        dim3 grid(NPIX / 64, QKV_CH / 64);
        gemm_kernel<<<grid, 256>>>(w_qkv, xln, nullptr, qkvb, QKV_CH, C_DIM, NPIX);
    }

    // 3. depthwise 3x3 + bias
    dwconv_kernel<<<(QKV_CH * NPIX) / 256, 256>>>(qkvb, w_dw, b_dw, qkvdw);

    // 4. attention per head -> att [192,4096]
    {
        dim3 grid(NPIX / 128, HEADS);
        attn_kernel<<<grid, 128>>>(qkvdw, temper, att);
    }

    // 5. out = w_proj @ att + x
    {
        dim3 grid(NPIX / 64, C_DIM / 64);
        gemm_kernel<<<grid, 256>>>(w_proj, att, x, out, C_DIM, C_DIM, NPIX);
    }
}